// round 8
// baseline (speedup 1.0000x reference)
#include <cuda_runtime.h>
#include <math.h>

#define TT 512
#define BB 64
#define VV 256
#define EE 512
#define HH 512

#define GRID_REC 128
#define NTH 512

#define WCOL  257      // ull2 stride per (d,col) weight column (padded, conflict-free)
#define SROWF 520      // float stride per state row (pad 8 -> conflict-free quads)

typedef unsigned long long ull;
__device__ __forceinline__ ull pk2(float x, float y) {
    ull r; asm("mov.b64 %0,{%1,%2};" : "=l"(r) : "f"(x), "f"(y)); return r;
}
__device__ __forceinline__ ull pkd(float x) {
    ull r; asm("mov.b64 %0,{%1,%1};" : "=l"(r) : "f"(x)); return r;
}
__device__ __forceinline__ ull fma2(ull a, ull b, ull c) {
    ull d; asm("fma.rn.f32x2 %0,%1,%2,%3;" : "=l"(d) : "l"(a), "l"(b), "l"(c)); return d;
}
__device__ __forceinline__ ull add2(ull a, ull b) {
    ull d; asm("add.rn.f32x2 %0,%1,%2;" : "=l"(d) : "l"(a), "l"(b)); return d;
}
__device__ __forceinline__ float2 upk2(ull a) {
    float2 r; asm("mov.b64 {%0,%1},%2;" : "=f"(r.x), "=f"(r.y) : "l"(a)); return r;
}

// ---------------------------------------------------------------------------
__device__ float g_table_t[2 * HH * VV];          // [j][v] : (emb @ w_in[0])^T
__device__ float g_stateA[BB * HH];               // state ping [b][k]
__device__ float g_stateB[BB * HH];               // state pong [b][k]
__device__ float g_out0[TT][HH * BB];             // layer-0 outputs [t][h][b]
__device__ float g_out1[TT][HH * BB];             // layer-1 outputs [t][h][b]
__device__ float g_in1[TT][2 * HH * BB];          // layer-1 input preact [t][j][b]
__device__ unsigned g_cnt[2 * 8 * 32];            // 8 spread counters per rowgroup

__global__ void k_reset() {
    int idx = blockIdx.x * blockDim.x + threadIdx.x;
    if (idx < 2 * 8 * 32) g_cnt[idx] = 0u;
}

__global__ void k_zero() {        // zero state ping buffer (pass entry condition)
    int idx = blockIdx.x * blockDim.x + threadIdx.x;
    if (idx < BB * HH) g_stateA[idx] = 0.0f;
}

// ---------------------------------------------------------------------------
__global__ void k_table(const float* __restrict__ emb,
                        const float* __restrict__ w_in) {
    int v = blockIdx.x;
    int j = threadIdx.x * 4;
    const float* er = emb + v * EE;
    float4 acc = make_float4(0.f, 0.f, 0.f, 0.f);
#pragma unroll 4
    for (int e = 0; e < EE; ++e) {
        float ev = er[e];
        float4 wv = *reinterpret_cast<const float4*>(w_in + (size_t)e * (2 * HH) + j);
        acc.x = fmaf(ev, wv.x, acc.x);
        acc.y = fmaf(ev, wv.y, acc.y);
        acc.z = fmaf(ev, wv.z, acc.z);
        acc.w = fmaf(ev, wv.w, acc.w);
    }
    g_table_t[(j + 0) * VV + v] = acc.x;
    g_table_t[(j + 1) * VV + v] = acc.y;
    g_table_t[(j + 2) * VV + v] = acc.z;
    g_table_t[(j + 3) * VV + v] = acc.w;
}

// ---------------------------------------------------------------------------
__device__ __forceinline__ void mbar_wait(unsigned mbar, unsigned parity) {
    asm volatile(
        "{\n\t.reg .pred P;\n\t"
        "LW_%=:\n\t"
        "mbarrier.try_wait.parity.acquire.cta.shared::cta.b64 P,[%0],%1,0x989680;\n\t"
        "@P bra LD_%=;\n\t"
        "bra LW_%=;\n\t"
        "LD_%=:\n\t}"
        :: "r"(mbar), "r"(parity) : "memory");
}

// ---------------------------------------------------------------------------
// Persistent RHN pass. 128 CTAs = 2 rowgroup domains x 64 colgroups.
// CTA tile: 32 rows x 8 h-cols. 512 thr: warp = 4 rows x 8 cols, k split in 2.
// Sync: 8 spread red.release counters / rowgroup; warp0 lanes 0-7 poll.
// Staging: 32 row-wise 2KB TMA copies into padded SMEM (conflict-free, no
// rotation ALU), all completing on one mbarrier.
// ---------------------------------------------------------------------------
template <int PASS>
__global__ void __launch_bounds__(NTH, 1) k_rhn(
    const int*   __restrict__ x,
    const float* __restrict__ w_h,
    const float* __restrict__ b_h)
{
    extern __shared__ float smraw[];
    ulonglong2* w_pk    = reinterpret_cast<ulonglong2*>(smraw);          // [4][8][WCOL] 131584 B
    float*      s_sh    = smraw + 32896;                                 // [32][520]     66560 B
    float2*     scratch = reinterpret_cast<float2*>(s_sh + 32 * SROWF);  // [32][8]        2048 B

    const int tid   = threadIdx.x;
    const int cid   = blockIdx.x;
    const int rg    = cid & 1;
    const int cg    = cid >> 1;
    const int w     = tid >> 5;
    const int lane  = tid & 31;
    const int rr    = lane >> 3;
    const int c     = lane & 7;
    const int wq    = w & 7;
    const int khalf = w >> 3;
    const int lrow  = wq * 4 + rr;
    const int grow  = rg * 32 + lrow;
    const int scol  = cg * 8 + c;

    unsigned smem_base;
    asm("{ .reg .u64 t; cvta.to.shared.u64 t, %1; cvt.u32.u64 %0, t; }"
        : "=r"(smem_base) : "l"(smraw));
    const unsigned ssh_a  = smem_base + 32896u * 4u;
    const unsigned mbar_a = smem_base + (32896u + 32u * SROWF + 512u) * 4u;

    if (tid == 0) {
        asm volatile("mbarrier.init.shared.b64 [%0], 1;" :: "r"(mbar_a) : "memory");
    }

    // ---- stage weights (h,g,k-pair packed, padded) ----
    for (int idx = tid; idx < 4 * 256 * 8; idx += NTH) {
        int cp = idx & 7;
        int kp = (idx >> 3) & 255;
        int d  = idx >> 11;
        const float* b0 = w_h + (((size_t)(PASS * 4 + d) * HH + 2 * kp) * (2 * HH)) + cg * 8 + cp;
        const float* b1 = b0 + 2 * HH;
        w_pk[(d * 8 + cp) * WCOL + kp] =
            make_ulonglong2(pk2(b0[0], b1[0]), pk2(b0[HH], b1[HH]));
    }

    float bh[4], bg[4];
#pragma unroll
    for (int d = 0; d < 4; ++d) {
        bh[d] = b_h[(size_t)(PASS * 4 + d) * (2 * HH) + scol];
        bg[d] = b_h[(size_t)(PASS * 4 + d) * (2 * HH) + HH + scol];
    }
    __syncthreads();

    const float* s_cur = g_stateA;
    float*       s_nxt = g_stateB;
    unsigned* cntbase = (unsigned*)&g_cnt[rg * 8 * 32];
    unsigned* my_cnt  = cntbase + ((cg & 7) * 32);
    const unsigned pbase = (unsigned)PASS * 2048u;

    const ulonglong2* s2  = reinterpret_cast<const ulonglong2*>(s_sh);
    const int rowbase = lrow * 130 + khalf * 64;   // ull2 index of this thread's window

    // prefetch t=0 input (khalf0 consumes it)
    float2 inp_cur = make_float2(0.f, 0.f);
    if (khalf == 0) {
        if (PASS == 0) {
            int xv = x[0 * BB + grow];
            inp_cur = make_float2(g_table_t[(size_t)scol * VV + xv],
                                  g_table_t[(size_t)(HH + scol) * VV + xv]);
        } else {
            inp_cur = make_float2(__ldcg(&g_in1[0][scol * BB + grow]),
                                  __ldcg(&g_in1[0][(HH + scol) * BB + grow]));
        }
    }

    unsigned sidx = 0;
    for (int t = 0; t < TT; ++t) {
        float2 inp_next = make_float2(0.f, 0.f);
        for (int d = 0; d < 4; ++d) {
            // ---- warp 0: wait peers' stores, then TMA-stage the state tile ----
            if (w == 0) {
                unsigned steps = pbase + sidx;
                if (lane < 8 && steps > 0) {
                    unsigned tgt = 8u * steps;
                    unsigned* cp_ = cntbase + lane * 32;
                    unsigned v;
                    do {
                        asm volatile("ld.acquire.gpu.global.u32 %0,[%1];"
                                     : "=r"(v) : "l"(cp_) : "memory");
                    } while (v < tgt);
                }
                __syncwarp();
                if (lane == 0) {
                    asm volatile("fence.proxy.async;" ::: "memory");
                    asm volatile("mbarrier.arrive.expect_tx.shared.b64 _, [%0], %1;"
                                 :: "r"(mbar_a), "n"(32 * HH * 4) : "memory");
                }
                __syncwarp();
                // 32 lanes: one 2KB row copy each into padded smem row
                asm volatile(
                    "cp.async.bulk.shared::cta.global.mbarrier::complete_tx::bytes [%0],[%1],%2,[%3];"
                    :: "r"(ssh_a + (unsigned)lane * (SROWF * 4u)),
                       "l"(s_cur + (size_t)(rg * 32 + lane) * HH),
                       "n"(HH * 4), "r"(mbar_a) : "memory");
            }
            mbar_wait(mbar_a, sidx & 1u);

            // prefetch next-t input during compute
            if (d == 0 && khalf == 0 && t + 1 < TT) {
                if (PASS == 0) {
                    int xv = x[(t + 1) * BB + grow];
                    inp_next = make_float2(g_table_t[(size_t)scol * VV + xv],
                                           g_table_t[(size_t)(HH + scol) * VV + xv]);
                } else {
                    inp_next = make_float2(__ldcg(&g_in1[t + 1][scol * BB + grow]),
                                           __ldcg(&g_in1[t + 1][(HH + scol) * BB + grow]));
                }
            }

            // ---- k-packed dot over this thread's 256 k's (straight walk) ----
            ull ah0 = pk2(0.f, 0.f), ag0 = pk2(0.f, 0.f);
            ull ah1 = pk2(0.f, 0.f), ag1 = pk2(0.f, 0.f);
            const ulonglong2* wp = w_pk + (size_t)(d * 8 + c) * WCOL + khalf * 128;
#pragma unroll 8
            for (int q = 0; q < 64; ++q) {
                ulonglong2 sv = s2[rowbase + q];
                ulonglong2 wA = wp[2 * q];
                ulonglong2 wB = wp[2 * q + 1];
                ah0 = fma2(sv.x, wA.x, ah0);
                ag0 = fma2(sv.x, wA.y, ag0);
                ah1 = fma2(sv.y, wB.x, ah1);
                ag1 = fma2(sv.y, wB.y, ag1);
            }
            float2 hp = upk2(add2(ah0, ah1));
            float2 gp = upk2(add2(ag0, ag1));
            float h_part = hp.x + hp.y;
            float g_part = gp.x + gp.y;

            if (khalf == 1) scratch[lrow * 8 + c] = make_float2(h_part, g_part);
            __syncthreads();

            if (khalf == 0) {
                float2 o = scratch[lrow * 8 + c];
                float acc_h = bh[d] + h_part + o.x;
                float acc_g = bg[d] + g_part + o.y;
                if (d == 0) { acc_h += inp_cur.x; acc_g += inp_cur.y; }

                float s_old = s_sh[lrow * SROWF + scol];
                float gt = 1.0f / (1.0f + expf(-acc_g));
                float ht = tanhf(acc_h);
                float s_new = ht * gt + s_old * (1.0f - gt);

                s_nxt[(size_t)grow * HH + scol] = s_new;
                if (d == 3) {
                    float* ob = (PASS == 0) ? g_out0[t] : g_out1[t];
                    ob[scol * BB + grow] = s_new;
                }
            }

            __syncthreads();                 // all STGs issued before arrive
            if (tid == 0) {
                asm volatile("red.release.gpu.global.add.u32 [%0], 1;"
                             :: "l"(my_cnt) : "memory");
            }

            const float* tmp = s_nxt;
            s_nxt = (float*)s_cur;
            s_cur = tmp;
            ++sidx;
        }
        inp_cur = inp_next;
    }
}

// ---------------------------------------------------------------------------
// g_in1[t][j][b] = sum_h g_out0[t][h][b] * w_in[1][h][j]   (FFMA2)
// ---------------------------------------------------------------------------
__global__ void k_inp1(const float* __restrict__ w_in) {
    int bid = blockIdx.x;
    int t   = bid >> 4;
    int jb  = bid & 15;
    int tid = threadIdx.x;
    int b   = tid & 63;
    int js  = tid >> 6;
    int j0  = jb * 64 + js * 16;

    ull acc[8];
#pragma unroll
    for (int i = 0; i < 8; ++i) acc[i] = pk2(0.f, 0.f);

    const float* o  = g_out0[t];
    const float* w1 = w_in + (size_t)EE * (2 * HH);
#pragma unroll 2
    for (int h = 0; h < HH; ++h) {
        ull svp = pkd(o[h * BB + b]);
        const ulonglong2* wr = reinterpret_cast<const ulonglong2*>(w1 + (size_t)h * (2 * HH) + j0);
        ulonglong2 q0 = wr[0], q1 = wr[1], q2 = wr[2], q3 = wr[3];
        acc[0] = fma2(svp, q0.x, acc[0]);  acc[1] = fma2(svp, q0.y, acc[1]);
        acc[2] = fma2(svp, q1.x, acc[2]);  acc[3] = fma2(svp, q1.y, acc[3]);
        acc[4] = fma2(svp, q2.x, acc[4]);  acc[5] = fma2(svp, q2.y, acc[5]);
        acc[6] = fma2(svp, q3.x, acc[6]);  acc[7] = fma2(svp, q3.y, acc[7]);
    }
#pragma unroll
    for (int i = 0; i < 8; ++i) {
        float2 v = upk2(acc[i]);
        g_in1[t][(j0 + 2 * i) * BB + b]     = v.x;
        g_in1[t][(j0 + 2 * i + 1) * BB + b] = v.y;
    }
}

// ---------------------------------------------------------------------------
__global__ void k_logits(const float* __restrict__ w_fc,
                         const float* __restrict__ b_fc,
                         float* __restrict__ out) {
    int bid = blockIdx.x;
    int t   = bid >> 2;
    int vb  = bid & 3;
    int tid = threadIdx.x;
    int b   = tid & 63;
    int vs  = tid >> 6;
    int v0  = vb * 64 + vs * 16;

    ull acc[8];
    const ulonglong2* bp = reinterpret_cast<const ulonglong2*>(b_fc + v0);
#pragma unroll
    for (int i = 0; i < 4; ++i) {
        ulonglong2 bq = bp[i];
        acc[2 * i] = bq.x; acc[2 * i + 1] = bq.y;
    }

    const float* o = g_out1[t];
#pragma unroll 2
    for (int h = 0; h < HH; ++h) {
        ull svp = pkd(o[h * BB + b]);
        const ulonglong2* wr = reinterpret_cast<const ulonglong2*>(w_fc + (size_t)h * VV + v0);
        ulonglong2 q0 = wr[0], q1 = wr[1], q2 = wr[2], q3 = wr[3];
        acc[0] = fma2(svp, q0.x, acc[0]);  acc[1] = fma2(svp, q0.y, acc[1]);
        acc[2] = fma2(svp, q1.x, acc[2]);  acc[3] = fma2(svp, q1.y, acc[3]);
        acc[4] = fma2(svp, q2.x, acc[4]);  acc[5] = fma2(svp, q2.y, acc[5]);
        acc[6] = fma2(svp, q3.x, acc[6]);  acc[7] = fma2(svp, q3.y, acc[7]);
    }

    ull* dst = reinterpret_cast<ull*>(out + ((size_t)(t * BB + b)) * VV + v0);
#pragma unroll
    for (int i = 0; i < 8; ++i) dst[i] = acc[i];
}

// ---------------------------------------------------------------------------
__global__ void k_sfinal(float* __restrict__ out, int l) {
    int idx = blockIdx.x * blockDim.x + threadIdx.x;
    if (idx >= BB * HH) return;
    out[(size_t)TT * BB * VV + (size_t)l * BB * HH + idx] = g_stateA[idx];
}

// ---------------------------------------------------------------------------
extern "C" void kernel_launch(void* const* d_in, const int* in_sizes, int n_in,
                              void* d_out, int out_size) {
    const int*   x    = (const int*)  d_in[0];
    const float* emb  = (const float*)d_in[1];
    const float* w_in = (const float*)d_in[2];
    const float* w_h  = (const float*)d_in[3];
    const float* b_h  = (const float*)d_in[4];
    const float* w_fc = (const float*)d_in[5];
    const float* b_fc = (const float*)d_in[6];
    float* out = (float*)d_out;

    // 131584 (weights) + 66560 (state, padded) + 2048 (scratch) + 16 (mbar)
    const int smem_bytes = 131584 + 32 * SROWF * 4 + 2048 + 16;
    static bool attr_done = false;
    if (!attr_done) {
        cudaFuncSetAttribute(k_rhn<0>, cudaFuncAttributeMaxDynamicSharedMemorySize, smem_bytes);
        cudaFuncSetAttribute(k_rhn<1>, cudaFuncAttributeMaxDynamicSharedMemorySize, smem_bytes);
        attr_done = true;
    }

    const bool has_sfinal = (out_size >= TT * BB * VV + 2 * BB * HH);

    k_reset<<<2, 256>>>();                                              // 1
    k_table<<<VV, 256>>>(emb, w_in);                                    // 2
    k_zero<<<(BB * HH + 255) / 256, 256>>>();                           // 3
    k_rhn<0><<<GRID_REC, NTH, smem_bytes>>>(x, w_h, b_h);               // 4 <- profiled
    if (has_sfinal)
        k_sfinal<<<(BB * HH + 255) / 256, 256>>>(out, 0);
    k_inp1<<<TT * 16, 256>>>(w_in);
    k_zero<<<(BB * HH + 255) / 256, 256>>>();
    k_rhn<1><<<GRID_REC, NTH, smem_bytes>>>(x, w_h, b_h);
    k_logits<<<TT * 4, 256>>>(w_fc, b_fc, out);
    if (has_sfinal)
        k_sfinal<<<(BB * HH + 255) / 256, 256>>>(out, 1);
}

// round 9
// speedup vs baseline: 1.0017x; 1.0017x over previous
#include <cuda_runtime.h>
#include <math.h>

#define TT 512
#define BB 64
#define VV 256
#define EE 512
#define HH 512

#define GRID_REC 128
#define NTH 512

#define WCOL  257      // ull2 stride per (d,col) weight column (padded, conflict-free)
#define SROWF 520      // float stride per state row (padded, conflict-free)

typedef unsigned long long ull;
__device__ __forceinline__ ull pk2(float x, float y) {
    ull r; asm("mov.b64 %0,{%1,%2};" : "=l"(r) : "f"(x), "f"(y)); return r;
}
__device__ __forceinline__ ull pkd(float x) {
    ull r; asm("mov.b64 %0,{%1,%1};" : "=l"(r) : "f"(x)); return r;
}
__device__ __forceinline__ ull fma2(ull a, ull b, ull c) {
    ull d; asm("fma.rn.f32x2 %0,%1,%2,%3;" : "=l"(d) : "l"(a), "l"(b), "l"(c)); return d;
}
__device__ __forceinline__ ull add2(ull a, ull b) {
    ull d; asm("add.rn.f32x2 %0,%1,%2;" : "=l"(d) : "l"(a), "l"(b)); return d;
}
__device__ __forceinline__ float2 upk2(ull a) {
    float2 r; asm("mov.b64 {%0,%1},%2;" : "=f"(r.x), "=f"(r.y) : "l"(a)); return r;
}

// ---------------------------------------------------------------------------
__device__ float g_table_t[2 * HH * VV];          // [j][v] : (emb @ w_in[0])^T
__device__ float g_stateA[BB * HH];               // state ping [b][k]
__device__ float g_stateB[BB * HH];               // state pong [b][k]
__device__ float g_out0[TT][HH * BB];             // layer-0 outputs [t][h][b]
__device__ float g_out1[TT][HH * BB];             // layer-1 outputs [t][h][b]
__device__ float g_in1[TT][2 * HH * BB];          // layer-1 input preact [t][j][b]
__device__ unsigned g_cnt[2 * 8 * 32];            // 8 spread counters per rowgroup

__global__ void k_reset() {
    int idx = blockIdx.x * blockDim.x + threadIdx.x;
    if (idx < 2 * 8 * 32) g_cnt[idx] = 0u;
}

__global__ void k_zero() {
    int idx = blockIdx.x * blockDim.x + threadIdx.x;
    if (idx < BB * HH) g_stateA[idx] = 0.0f;
}

// ---------------------------------------------------------------------------
__global__ void k_table(const float* __restrict__ emb,
                        const float* __restrict__ w_in) {
    int v = blockIdx.x;
    int j = threadIdx.x * 4;
    const float* er = emb + v * EE;
    float4 acc = make_float4(0.f, 0.f, 0.f, 0.f);
#pragma unroll 4
    for (int e = 0; e < EE; ++e) {
        float ev = er[e];
        float4 wv = *reinterpret_cast<const float4*>(w_in + (size_t)e * (2 * HH) + j);
        acc.x = fmaf(ev, wv.x, acc.x);
        acc.y = fmaf(ev, wv.y, acc.y);
        acc.z = fmaf(ev, wv.z, acc.z);
        acc.w = fmaf(ev, wv.w, acc.w);
    }
    g_table_t[(j + 0) * VV + v] = acc.x;
    g_table_t[(j + 1) * VV + v] = acc.y;
    g_table_t[(j + 2) * VV + v] = acc.z;
    g_table_t[(j + 3) * VV + v] = acc.w;
}

// ---------------------------------------------------------------------------
__device__ __forceinline__ void mbar_wait(unsigned mbar, unsigned parity) {
    asm volatile(
        "{\n\t.reg .pred P;\n\t"
        "LW_%=:\n\t"
        "mbarrier.try_wait.parity.acquire.cta.shared::cta.b64 P,[%0],%1,0x989680;\n\t"
        "@P bra LD_%=;\n\t"
        "bra LW_%=;\n\t"
        "LD_%=:\n\t}"
        :: "r"(mbar), "r"(parity) : "memory");
}

// ---------------------------------------------------------------------------
// Persistent RHN pass. 128 CTAs = 2 rowgroup domains (cid>>6) x 64 colgroups.
// 4-CTA clusters (consecutive cids, never straddle a rowgroup).
// Per step: cluster leader polls spread counters, then issues 32 row-wise 2KB
// MULTICAST TMA copies (one per lane of warp0) into the padded SMEM state tile
// of all 4 cluster CTAs. Members just park on their local mbar (prearmed
// expect_tx). 4x less L2 state traffic, 4x fewer TMA streams, 16 pollers total.
// ---------------------------------------------------------------------------
template <int PASS>
__global__ void __cluster_dims__(4, 1, 1) __launch_bounds__(NTH, 1) k_rhn(
    const int*   __restrict__ x,
    const float* __restrict__ w_h,
    const float* __restrict__ b_h)
{
    extern __shared__ float smraw[];
    ulonglong2* w_pk    = reinterpret_cast<ulonglong2*>(smraw);          // 131584 B
    float*      s_sh    = smraw + 32896;                                 // [32][520] 66560 B
    float2*     scratch = reinterpret_cast<float2*>(s_sh + 32 * SROWF);  // 2048 B

    const int tid   = threadIdx.x;
    const int cid   = blockIdx.x;
    const int rg    = cid >> 6;
    const int cg    = cid & 63;
    const int w     = tid >> 5;
    const int lane  = tid & 31;
    const int rr    = lane >> 3;
    const int c     = lane & 7;
    const int wq    = w & 7;
    const int khalf = w >> 3;
    const int lrow  = wq * 4 + rr;
    const int grow  = rg * 32 + lrow;
    const int scol  = cg * 8 + c;

    unsigned crank;
    asm("mov.u32 %0, %%cluster_ctarank;" : "=r"(crank));

    unsigned smem_base;
    asm("{ .reg .u64 t; cvta.to.shared.u64 t, %1; cvt.u32.u64 %0, t; }"
        : "=r"(smem_base) : "l"(smraw));
    const unsigned ssh_a  = smem_base + 131584u;
    const unsigned mbar_a = smem_base + 200192u;

    if (tid == 0) {
        asm volatile("mbarrier.init.shared.b64 [%0], 1;" :: "r"(mbar_a) : "memory");
    }

    // ---- stage weights (h,g,k-pair packed, padded) ----
    for (int idx = tid; idx < 4 * 256 * 8; idx += NTH) {
        int cp = idx & 7;
        int kp = (idx >> 3) & 255;
        int d  = idx >> 11;
        const float* b0 = w_h + (((size_t)(PASS * 4 + d) * HH + 2 * kp) * (2 * HH)) + cg * 8 + cp;
        const float* b1 = b0 + 2 * HH;
        w_pk[(d * 8 + cp) * WCOL + kp] =
            make_ulonglong2(pk2(b0[0], b1[0]), pk2(b0[HH], b1[HH]));
    }

    float bh[4], bg[4];
#pragma unroll
    for (int d = 0; d < 4; ++d) {
        bh[d] = b_h[(size_t)(PASS * 4 + d) * (2 * HH) + scol];
        bg[d] = b_h[(size_t)(PASS * 4 + d) * (2 * HH) + HH + scol];
    }
    __syncthreads();

    // prearm expect_tx for step 0 (arrival + tx budget for phase 0)
    if (tid == 0) {
        asm volatile("mbarrier.arrive.expect_tx.shared.b64 _, [%0], %1;"
                     :: "r"(mbar_a), "n"(32 * HH * 4) : "memory");
    }
    __syncthreads();
    // all cluster CTAs' mbars initialized+prearmed before any leader TMA
    asm volatile("barrier.cluster.arrive.aligned;" ::: "memory");
    asm volatile("barrier.cluster.wait.aligned;" ::: "memory");

    const float* s_cur = g_stateA;
    float*       s_nxt = g_stateB;
    unsigned* cntbase = (unsigned*)&g_cnt[rg * 8 * 32];
    unsigned* my_cnt  = cntbase + ((cg & 7) * 32);
    const unsigned pbase = (unsigned)PASS * 2048u;

    const ulonglong2* s2  = reinterpret_cast<const ulonglong2*>(s_sh);
    const int rowbase = lrow * 130 + khalf * 64;   // ull2 index (row stride 130 ull2)

    // prefetch t=0 input (khalf0 consumes it)
    float2 inp_cur = make_float2(0.f, 0.f);
    if (khalf == 0) {
        if (PASS == 0) {
            int xv = x[0 * BB + grow];
            inp_cur = make_float2(g_table_t[(size_t)scol * VV + xv],
                                  g_table_t[(size_t)(HH + scol) * VV + xv]);
        } else {
            inp_cur = make_float2(__ldcg(&g_in1[0][scol * BB + grow]),
                                  __ldcg(&g_in1[0][(HH + scol) * BB + grow]));
        }
    }

    unsigned sidx = 0;
    for (int t = 0; t < TT; ++t) {
        float2 inp_next = make_float2(0.f, 0.f);
        for (int d = 0; d < 4; ++d) {
            // ---- cluster leader warp: wait peers' stores, multicast-stage tile
            if (w == 0 && crank == 0) {
                unsigned steps = pbase + sidx;
                if (lane < 8 && steps > 0) {
                    unsigned tgt = 8u * steps;
                    unsigned* cp_ = cntbase + lane * 32;
                    unsigned v;
                    do {
                        asm volatile("ld.acquire.gpu.global.u32 %0,[%1];"
                                     : "=r"(v) : "l"(cp_) : "memory");
                    } while (v < tgt);
                }
                __syncwarp();
                asm volatile("fence.proxy.async;" ::: "memory");
                // 32 lanes: one padded-row 2KB multicast copy each (mask 0xF)
                asm volatile(
                    "cp.async.bulk.shared::cluster.global.mbarrier::complete_tx::bytes"
                    ".multicast::cluster [%0],[%1],%2,[%3],%4;"
                    :: "r"(ssh_a + (unsigned)lane * (SROWF * 4u)),
                       "l"(s_cur + (size_t)(rg * 32 + lane) * HH),
                       "n"(HH * 4), "r"(mbar_a), "h"((unsigned short)0xF) : "memory");
            }
            mbar_wait(mbar_a, sidx & 1u);
            // prearm next phase immediately (before our red arrival -> safe)
            if (tid == 0) {
                asm volatile("mbarrier.arrive.expect_tx.shared.b64 _, [%0], %1;"
                             :: "r"(mbar_a), "n"(32 * HH * 4) : "memory");
            }

            // prefetch next-t input during compute
            if (d == 0 && khalf == 0 && t + 1 < TT) {
                if (PASS == 0) {
                    int xv = x[(t + 1) * BB + grow];
                    inp_next = make_float2(g_table_t[(size_t)scol * VV + xv],
                                           g_table_t[(size_t)(HH + scol) * VV + xv]);
                } else {
                    inp_next = make_float2(__ldcg(&g_in1[t + 1][scol * BB + grow]),
                                           __ldcg(&g_in1[t + 1][(HH + scol) * BB + grow]));
                }
            }

            // ---- k-packed dot over this thread's 256 k's (straight walk) ----
            ull ah0 = pk2(0.f, 0.f), ag0 = pk2(0.f, 0.f);
            ull ah1 = pk2(0.f, 0.f), ag1 = pk2(0.f, 0.f);
            const ulonglong2* wp = w_pk + (size_t)(d * 8 + c) * WCOL + khalf * 128;
#pragma unroll 8
            for (int q = 0; q < 64; ++q) {
                ulonglong2 sv = s2[rowbase + q];
                ulonglong2 wA = wp[2 * q];
                ulonglong2 wB = wp[2 * q + 1];
                ah0 = fma2(sv.x, wA.x, ah0);
                ag0 = fma2(sv.x, wA.y, ag0);
                ah1 = fma2(sv.y, wB.x, ah1);
                ag1 = fma2(sv.y, wB.y, ag1);
            }
            float2 hp = upk2(add2(ah0, ah1));
            float2 gp = upk2(add2(ag0, ag1));
            float h_part = hp.x + hp.y;
            float g_part = gp.x + gp.y;

            if (khalf == 1) scratch[lrow * 8 + c] = make_float2(h_part, g_part);
            __syncthreads();

            if (khalf == 0) {
                float2 o = scratch[lrow * 8 + c];
                float acc_h = bh[d] + h_part + o.x;
                float acc_g = bg[d] + g_part + o.y;
                if (d == 0) { acc_h += inp_cur.x; acc_g += inp_cur.y; }

                float s_old = s_sh[lrow * SROWF + scol];
                float gt = 1.0f / (1.0f + expf(-acc_g));
                float ht = tanhf(acc_h);
                float s_new = ht * gt + s_old * (1.0f - gt);

                s_nxt[(size_t)grow * HH + scol] = s_new;
                if (d == 3) {
                    float* ob = (PASS == 0) ? g_out0[t] : g_out1[t];
                    ob[scol * BB + grow] = s_new;
                }
            }

            __syncthreads();                 // all STGs issued before arrive
            if (tid == 0) {
                asm volatile("red.release.gpu.global.add.u32 [%0], 1;"
                             :: "l"(my_cnt) : "memory");
            }

            const float* tmp = s_nxt;
            s_nxt = (float*)s_cur;
            s_cur = tmp;
            ++sidx;
        }
        inp_cur = inp_next;
    }
}

// ---------------------------------------------------------------------------
// g_in1[t][j][b] = sum_h g_out0[t][h][b] * w_in[1][h][j]   (FFMA2)
// ---------------------------------------------------------------------------
__global__ void k_inp1(const float* __restrict__ w_in) {
    int bid = blockIdx.x;
    int t   = bid >> 4;
    int jb  = bid & 15;
    int tid = threadIdx.x;
    int b   = tid & 63;
    int js  = tid >> 6;
    int j0  = jb * 64 + js * 16;

    ull acc[8];
#pragma unroll
    for (int i = 0; i < 8; ++i) acc[i] = pk2(0.f, 0.f);

    const float* o  = g_out0[t];
    const float* w1 = w_in + (size_t)EE * (2 * HH);
#pragma unroll 2
    for (int h = 0; h < HH; ++h) {
        ull svp = pkd(o[h * BB + b]);
        const ulonglong2* wr = reinterpret_cast<const ulonglong2*>(w1 + (size_t)h * (2 * HH) + j0);
        ulonglong2 q0 = wr[0], q1 = wr[1], q2 = wr[2], q3 = wr[3];
        acc[0] = fma2(svp, q0.x, acc[0]);  acc[1] = fma2(svp, q0.y, acc[1]);
        acc[2] = fma2(svp, q1.x, acc[2]);  acc[3] = fma2(svp, q1.y, acc[3]);
        acc[4] = fma2(svp, q2.x, acc[4]);  acc[5] = fma2(svp, q2.y, acc[5]);
        acc[6] = fma2(svp, q3.x, acc[6]);  acc[7] = fma2(svp, q3.y, acc[7]);
    }
#pragma unroll
    for (int i = 0; i < 8; ++i) {
        float2 v = upk2(acc[i]);
        g_in1[t][(j0 + 2 * i) * BB + b]     = v.x;
        g_in1[t][(j0 + 2 * i + 1) * BB + b] = v.y;
    }
}

// ---------------------------------------------------------------------------
__global__ void k_logits(const float* __restrict__ w_fc,
                         const float* __restrict__ b_fc,
                         float* __restrict__ out) {
    int bid = blockIdx.x;
    int t   = bid >> 2;
    int vb  = bid & 3;
    int tid = threadIdx.x;
    int b   = tid & 63;
    int vs  = tid >> 6;
    int v0  = vb * 64 + vs * 16;

    ull acc[8];
    const ulonglong2* bp = reinterpret_cast<const ulonglong2*>(b_fc + v0);
#pragma unroll
    for (int i = 0; i < 4; ++i) {
        ulonglong2 bq = bp[i];
        acc[2 * i] = bq.x; acc[2 * i + 1] = bq.y;
    }

    const float* o = g_out1[t];
#pragma unroll 2
    for (int h = 0; h < HH; ++h) {
        ull svp = pkd(o[h * BB + b]);
        const ulonglong2* wr = reinterpret_cast<const ulonglong2*>(w_fc + (size_t)h * VV + v0);
        ulonglong2 q0 = wr[0], q1 = wr[1], q2 = wr[2], q3 = wr[3];
        acc[0] = fma2(svp, q0.x, acc[0]);  acc[1] = fma2(svp, q0.y, acc[1]);
        acc[2] = fma2(svp, q1.x, acc[2]);  acc[3] = fma2(svp, q1.y, acc[3]);
        acc[4] = fma2(svp, q2.x, acc[4]);  acc[5] = fma2(svp, q2.y, acc[5]);
        acc[6] = fma2(svp, q3.x, acc[6]);  acc[7] = fma2(svp, q3.y, acc[7]);
    }

    ull* dst = reinterpret_cast<ull*>(out + ((size_t)(t * BB + b)) * VV + v0);
#pragma unroll
    for (int i = 0; i < 8; ++i) dst[i] = acc[i];
}

// ---------------------------------------------------------------------------
__global__ void k_sfinal(float* __restrict__ out, int l) {
    int idx = blockIdx.x * blockDim.x + threadIdx.x;
    if (idx >= BB * HH) return;
    out[(size_t)TT * BB * VV + (size_t)l * BB * HH + idx] = g_stateA[idx];
}

// ---------------------------------------------------------------------------
extern "C" void kernel_launch(void* const* d_in, const int* in_sizes, int n_in,
                              void* d_out, int out_size) {
    const int*   x    = (const int*)  d_in[0];
    const float* emb  = (const float*)d_in[1];
    const float* w_in = (const float*)d_in[2];
    const float* w_h  = (const float*)d_in[3];
    const float* b_h  = (const float*)d_in[4];
    const float* w_fc = (const float*)d_in[5];
    const float* b_fc = (const float*)d_in[6];
    float* out = (float*)d_out;

    // 131584 (weights) + 66560 (state) + 2048 (scratch) + 16 (mbar) = 200208 B
    const int smem_bytes = 131584 + 32 * SROWF * 4 + 2048 + 16;
    static bool attr_done = false;
    if (!attr_done) {
        cudaFuncSetAttribute(k_rhn<0>, cudaFuncAttributeMaxDynamicSharedMemorySize, smem_bytes);
        cudaFuncSetAttribute(k_rhn<1>, cudaFuncAttributeMaxDynamicSharedMemorySize, smem_bytes);
        attr_done = true;
    }

    const bool has_sfinal = (out_size >= TT * BB * VV + 2 * BB * HH);

    k_reset<<<2, 256>>>();                                              // 1
    k_table<<<VV, 256>>>(emb, w_in);                                    // 2
    k_zero<<<(BB * HH + 255) / 256, 256>>>();                           // 3
    k_rhn<0><<<GRID_REC, NTH, smem_bytes>>>(x, w_h, b_h);               // 4 <- profiled
    if (has_sfinal)
        k_sfinal<<<(BB * HH + 255) / 256, 256>>>(out, 0);
    k_inp1<<<TT * 16, 256>>>(w_in);
    k_zero<<<(BB * HH + 255) / 256, 256>>>();
    k_rhn<1><<<GRID_REC, NTH, smem_bytes>>>(x, w_h, b_h);
    k_logits<<<TT * 4, 256>>>(w_fc, b_fc, out);
    if (has_sfinal)
        k_sfinal<<<(BB * HH + 255) / 256, 256>>>(out, 1);
}